// round 15
// baseline (speedup 1.0000x reference)
#include <cuda_runtime.h>
#include <cstdint>

#define NB       4
#define NN       2048
#define CLAMP_V  10.0f

typedef unsigned long long ull;

// Partial G (8 d-slices): [8][NB*NN][32] floats = 8 MB (no allocs allowed)
__device__ __align__(16) float g_Gp[8 * NB * NN * 32];
// Reduced G + row squared-norms
__device__ __align__(16) float g_G[NB * NN * 32];
__device__ __align__(16) float g_Gsq[NB * NN];

// ---------------- packed f32x2 helpers (FFMA2 via PTX) ----------------
__device__ __forceinline__ ull ffma2(ull a, ull b, ull c) {
    ull d;
    asm("fma.rn.f32x2 %0, %1, %2, %3;" : "=l"(d) : "l"(a), "l"(b), "l"(c));
    return d;
}
__device__ __forceinline__ ull pack2(float x, float y) {
    ull r;
    asm("mov.b64 %0, {%1, %2};" : "=l"(r) : "f"(x), "f"(y));
    return r;
}
__device__ __forceinline__ float2 unpack2(ull v) {
    float2 f;
    asm("mov.b64 {%0, %1}, %2;" : "=f"(f.x), "=f"(f.y) : "l"(v));
    return f;
}
__device__ __forceinline__ float hadd2(ull v) {
    float2 f = unpack2(v);
    return f.x + f.y;
}

// ============================================================================
// Kernel 1 (barrier-free streaming): partial G[s][n][k], slice s = 128 d.
// 512 blocks (64 row-tiles x 8 slices) x 256 threads.
// H: direct LDG.128 (each row owned by exactly one thread-group -> L2 reads
// H once); W slice staged to smem ONCE (k,k+8 interleaved so a thread's 4
// k-values come from 2 LDS.128). Main loop: zero barriers, zero STS.
// Micro 4 rows x 4 k. Per thread: 1024 FFMA2, 128 LDG.128, 128 LDS.128.
// ============================================================================
__global__ __launch_bounds__(256)
void geom_proj_kernel(const float* __restrict__ H, const float* __restrict__ W) {
    // Ws2[dp][pos]: pos 2*kg -> k=kg, 2*kg+1 -> k=kg+8, 16+2*kg -> k=kg+16,
    // 17+2*kg -> k=kg+24.  Row stride 34 (even) keeps 16B alignment.
    __shared__ __align__(16) ull Ws2[64][34];

    const int tid   = threadIdx.x;
    const int kg    = tid & 7;         // k = kg + 8q
    const int ty    = tid >> 3;        // rows ty + 32*r  (0..31)
    const int slice = blockIdx.x & 7;
    const int n0    = (blockIdx.x >> 3) * 128;

    const float4* __restrict__ W4 = (const float4*)W;
    const float4* __restrict__ H4 = (const float4*)H;

    // ---- stage W slice once (64 dpairs x 32 k), interleaved layout
    #pragma unroll
    for (int t = 0; t < 4; t++) {
        int idx = tid + 256 * t;       // 0..1023
        int k = idx >> 5, f = idx & 31;
        float4 wv = W4[k * 256 + slice * 32 + f];
        int pos = (k < 8)  ? 2 * k
                : (k < 16) ? 2 * (k - 8) + 1
                : (k < 24) ? 16 + 2 * (k - 16)
                :            17 + 2 * (k - 24);
        Ws2[2 * f][pos]     = pack2(wv.x, wv.y);
        Ws2[2 * f + 1][pos] = pack2(wv.z, wv.w);
    }
    __syncthreads();                   // the ONLY barrier

    // row base pointers (float4 units); 32 f4 per row-slice
    const float4* hrow[4];
    #pragma unroll
    for (int r = 0; r < 4; r++)
        hrow[r] = H4 + (size_t)(n0 + ty + 32 * r) * 256 + slice * 32;

    ull acc[4][4];
    #pragma unroll
    for (int r = 0; r < 4; r++)
        #pragma unroll
        for (int q = 0; q < 4; q++) acc[r][q] = 0ULL;

    #pragma unroll 1
    for (int blk = 0; blk < 8; blk++) {     // 8 dpairs (4 f4 per row) per blk
        // batched H loads: 16 LDG.128 in flight
        float4 h4[4][4];
        #pragma unroll
        for (int r = 0; r < 4; r++)
            #pragma unroll
            for (int g = 0; g < 4; g++)
                h4[r][g] = __ldg(hrow[r] + blk * 4 + g);

        #pragma unroll
        for (int g = 0; g < 4; g++) {
            const int dpA = blk * 8 + 2 * g;
            // 4 LDS.128: q-pairs for dpA and dpA+1 (broadcast across ty)
            ulonglong2 wA01 = *(const ulonglong2*)&Ws2[dpA][2 * kg];
            ulonglong2 wA23 = *(const ulonglong2*)&Ws2[dpA][16 + 2 * kg];
            ulonglong2 wB01 = *(const ulonglong2*)&Ws2[dpA + 1][2 * kg];
            ulonglong2 wB23 = *(const ulonglong2*)&Ws2[dpA + 1][16 + 2 * kg];
            #pragma unroll
            for (int r = 0; r < 4; r++) {
                ull hA = pack2(h4[r][g].x, h4[r][g].y);
                ull hB = pack2(h4[r][g].z, h4[r][g].w);
                acc[r][0] = ffma2(hA, wA01.x, acc[r][0]);
                acc[r][1] = ffma2(hA, wA01.y, acc[r][1]);
                acc[r][2] = ffma2(hA, wA23.x, acc[r][2]);
                acc[r][3] = ffma2(hA, wA23.y, acc[r][3]);
                acc[r][0] = ffma2(hB, wB01.x, acc[r][0]);
                acc[r][1] = ffma2(hB, wB01.y, acc[r][1]);
                acc[r][2] = ffma2(hB, wB23.x, acc[r][2]);
                acc[r][3] = ffma2(hB, wB23.y, acc[r][3]);
            }
        }
    }

    float* __restrict__ Gp = g_Gp + (size_t)slice * (NB * NN * 32);
    #pragma unroll
    for (int r = 0; r < 4; r++) {
        const size_t rb = (size_t)(n0 + ty + 32 * r) * 32;
        #pragma unroll
        for (int q = 0; q < 4; q++)
            Gp[rb + kg + 8 * q] = hadd2(acc[r][q]);
    }
}

// ============================================================================
// Kernel 1.5: reduce the 8 d-slice partials -> g_G, and compute g_Gsq.
// ============================================================================
__global__ __launch_bounds__(128)
void reduce_g_kernel() {
    const int tid = threadIdx.x;
    const int row = blockIdx.x * 32 + (tid >> 2);   // global row 0..8191
    const int fq  = tid & 3;

    const float4* __restrict__ P = (const float4*)g_Gp;
    const size_t stride = (size_t)(NB * NN * 32) / 4;   // float4 units per slice
    float4* __restrict__ Go = (float4*)g_G;

    float sq = 0.f;
    #pragma unroll
    for (int h = 0; h < 2; h++) {
        const size_t idx = (size_t)row * 8 + fq + 4 * h;
        float4 s = P[idx];
        #pragma unroll
        for (int sl = 1; sl < 8; sl++) {
            float4 a = P[idx + sl * stride];
            s.x += a.x; s.y += a.y; s.z += a.z; s.w += a.w;
        }
        Go[idx] = s;
        sq += s.x * s.x + s.y * s.y + s.z * s.z + s.w * s.w;
    }
    sq += __shfl_xor_sync(0xFFFFFFFF, sq, 1);
    sq += __shfl_xor_sync(0xFFFFFFFF, sq, 2);
    if (fq == 0) g_Gsq[row] = sq;
}

// ============================================================================
// Kernel 2 (unchanged best): triangular-symmetric EMA update.
// Grid (528, 4); 128 threads; 64x64 tile; Gram micro 8(i) x 4(j).
// ============================================================================
#define GROW 18    // 16 kpairs + pad 2

__global__ __launch_bounds__(128)
void bias_update_kernel(const float* __restrict__ Bprev,
                        const float* __restrict__ alpha_p,
                        const float* __restrict__ beta_p,
                        float* __restrict__ Out) {
    __shared__ __align__(16) unsigned char gbuf[2][9216];  // Gi | Gj; later dist_t
    __shared__ __align__(16) float dist_s[64][68];
    __shared__ float gsqI[64];
    __shared__ float gsqJ[64];

    ull (*Gi)[GROW] = (ull(*)[GROW])gbuf[0];
    ull (*Gj)[GROW] = (ull(*)[GROW])gbuf[1];
    float (*dist_t)[68] = (float(*)[68])gbuf;              // 64*68*4 = 17408 <= 18432

    const int tid = threadIdx.x;
    const int tx  = tid & 15;      // Gram: j = tx + 16*jj
    const int ty  = tid >> 4;      // Gram: i = ty + 8*ii
    const int b   = blockIdx.y;

    // triangular decode: q -> (ti, tj), tj <= ti
    const int q = blockIdx.x;
    int ti = (int)((sqrtf(8.0f * (float)q + 1.0f) - 1.0f) * 0.5f);
    while ((ti + 1) * (ti + 2) / 2 <= q) ti++;
    while (ti * (ti + 1) / 2 > q) ti--;
    const int tj = q - ti * (ti + 1) / 2;
    const int i0 = ti * 64;
    const int j0 = tj * 64;
    const bool offd = (ti != tj);

    // ---- stage G tiles (single reduced source) + precomputed Gsq
    const float4* __restrict__ G4 = (const float4*)g_G;
    const size_t baseI = ((size_t)b * NN + i0) * 8;   // float4 units (8/row)
    const size_t baseJ = ((size_t)b * NN + j0) * 8;

    #pragma unroll
    for (int p = 0; p < 4; p++) {
        int idx = tid + 128 * p;               // 0..511
        int row = idx >> 3, fc = idx & 7;
        float4 a = G4[baseI + idx];
        *(float4*)&Gi[row][fc * 2] = a;
        float4 c = G4[baseJ + idx];
        *(float4*)&Gj[row][fc * 2] = c;
    }
    if (tid < 64)       gsqI[tid]      = g_Gsq[(size_t)b * NN + i0 + tid];
    else                gsqJ[tid - 64] = g_Gsq[(size_t)b * NN + j0 + (tid - 64)];
    __syncthreads();

    // ---- 8x4 Gram micro-tile (full operand staging)
    ull acc[8][4];
    #pragma unroll
    for (int ii = 0; ii < 8; ii++)
        #pragma unroll
        for (int jj = 0; jj < 4; jj++) acc[ii][jj] = 0ULL;

    #pragma unroll
    for (int kk2 = 0; kk2 < 8; kk2++) {
        ull a0[8], a1[8], b0[4], b1[4];
        #pragma unroll
        for (int ii = 0; ii < 8; ii++) {
            float4 t = *(const float4*)&Gi[ty + 8 * ii][kk2 * 2];
            a0[ii] = pack2(t.x, t.y);
            a1[ii] = pack2(t.z, t.w);
        }
        #pragma unroll
        for (int jj = 0; jj < 4; jj++) {
            float4 t = *(const float4*)&Gj[tx + 16 * jj][kk2 * 2];
            b0[jj] = pack2(t.x, t.y);
            b1[jj] = pack2(t.z, t.w);
        }
        #pragma unroll
        for (int ii = 0; ii < 8; ii++)
            #pragma unroll
            for (int jj = 0; jj < 4; jj++) {
                acc[ii][jj] = ffma2(a0[ii], b0[jj], acc[ii][jj]);
                acc[ii][jj] = ffma2(a1[ii], b1[jj], acc[ii][jj]);
            }
    }

    const float alpha = __ldg(alpha_p);
    const float beta  = __ldg(beta_p);

    // ---- Phase B: bd = beta*max(dist,0) into registers
    float bd[8][4];
    #pragma unroll
    for (int ii = 0; ii < 8; ii++) {
        const float si = gsqI[ty + 8 * ii];
        #pragma unroll
        for (int jj = 0; jj < 4; jj++) {
            float g = hadd2(acc[ii][jj]);
            float dist = si + gsqJ[tx + 16 * jj] - 2.0f * g;
            bd[ii][jj] = beta * fmaxf(dist, 0.0f);
        }
    }
    __syncthreads();               // all Gram smem reads done (dist_t aliases G)

    #pragma unroll
    for (int ii = 0; ii < 8; ii++) {
        const int il = ty + 8 * ii;
        #pragma unroll
        for (int jj = 0; jj < 4; jj++) {
            const int jl = tx + 16 * jj;
            dist_s[il][jl] = bd[ii][jj];
            if (offd) dist_t[jl][il] = bd[ii][jj];
        }
    }
    __syncthreads();

    // ---- Phase C: vectorized epilogue; all loads batched (MLP up to 16)
    const int c4 = tid & 15;       // float4 column
    const int rg = tid >> 4;       // row = rg + 8*rr
    const size_t obase = (size_t)b * NN * NN;

    float4 bp1[8], bp2[8];
    #pragma unroll
    for (int rr = 0; rr < 8; rr++) {
        const int row = rg + 8 * rr;
        bp1[rr] = __ldg((const float4*)(Bprev + obase + (size_t)(i0 + row) * NN + j0 + 4 * c4));
    }
    if (offd) {
        #pragma unroll
        for (int rr = 0; rr < 8; rr++) {
            const int row = rg + 8 * rr;
            bp2[rr] = __ldg((const float4*)(Bprev + obase + (size_t)(j0 + row) * NN + i0 + 4 * c4));
        }
    }

    #pragma unroll
    for (int rr = 0; rr < 8; rr++) {
        const int row = rg + 8 * rr;
        float4 d = *(const float4*)&dist_s[row][4 * c4];
        float4 v;
        v.x = fminf(fmaxf(fmaf(alpha, bp1[rr].x, -d.x), -CLAMP_V), CLAMP_V);
        v.y = fminf(fmaxf(fmaf(alpha, bp1[rr].y, -d.y), -CLAMP_V), CLAMP_V);
        v.z = fminf(fmaxf(fmaf(alpha, bp1[rr].z, -d.z), -CLAMP_V), CLAMP_V);
        v.w = fminf(fmaxf(fmaf(alpha, bp1[rr].w, -d.w), -CLAMP_V), CLAMP_V);
        *(float4*)(Out + obase + (size_t)(i0 + row) * NN + j0 + 4 * c4) = v;
    }
    if (offd) {
        #pragma unroll
        for (int rr = 0; rr < 8; rr++) {
            const int row = rg + 8 * rr;
            float4 d = *(const float4*)&dist_t[row][4 * c4];
            float4 v;
            v.x = fminf(fmaxf(fmaf(alpha, bp2[rr].x, -d.x), -CLAMP_V), CLAMP_V);
            v.y = fminf(fmaxf(fmaf(alpha, bp2[rr].y, -d.y), -CLAMP_V), CLAMP_V);
            v.z = fminf(fmaxf(fmaf(alpha, bp2[rr].z, -d.z), -CLAMP_V), CLAMP_V);
            v.w = fminf(fmaxf(fmaf(alpha, bp2[rr].w, -d.w), -CLAMP_V), CLAMP_V);
            *(float4*)(Out + obase + (size_t)(j0 + row) * NN + i0 + 4 * c4) = v;
        }
    }
}

// ============================================================================
extern "C" void kernel_launch(void* const* d_in, const int* in_sizes, int n_in,
                              void* d_out, int out_size) {
    const float* H     = (const float*)d_in[0];   // [4,2048,1024]
    const float* Bprev = (const float*)d_in[1];   // [4,2048,2048]
    const float* W     = (const float*)d_in[2];   // [32,1024]
    const float* alpha = (const float*)d_in[3];   // scalar
    const float* beta  = (const float*)d_in[4];   // scalar
    float* Out = (float*)d_out;

    geom_proj_kernel<<<512, 256>>>(H, W);
    reduce_g_kernel<<<256, 128>>>();
    bias_update_kernel<<<dim3(528, NB), 128>>>(Bprev, alpha, beta, Out);
}